// round 8
// baseline (speedup 1.0000x reference)
#include <cuda_runtime.h>
#include <cuda_bf16.h>
#include <math.h>

// BboxSemanticAtt: out[b,y,x] = sigmoid( sum_i c_i * [y1<=y<y2][x1<=x<x2] )
// preds: [B, 256, 5] f32; out: [B, 512, 512] f32.
//
// Dual-chunk warps for ILP: each warp owns TWO independent 8-row chunks
// (32 rows apart, same batch) and interleaves them, halving exposed latency
// of every serial chain (scan LDS, shfl scan, event LDS->FADD, MUFU).
// Build: one pass over boxes tests both anchors (box metadata read once).
// Row updates from per-row event buckets via broadcast LDS. v holds g/2
// (confidences pre-halved); sigmoid = 0.5*tanh(v)+0.5 (1 MUFU).

#define FEAT   512
#define NBOX   256
#define NWARPS 4
#define CHUNK  8
#define ROWS_PER_BLOCK 64                  // 4 warps x 2 chunks x 8 rows
#define ROW_WORDS 644                      // 512 data + 4 pad per 16 (+x2=512 slot)
#define ROW_V4   161
#define EVCAP  8

__device__ __forceinline__ int padw(int p) { return p + ((p >> 4) << 2); }

__global__ __launch_bounds__(128, 6)
void bbox_att_kernel(const float* __restrict__ preds,
                     float* __restrict__ out,
                     int blocksPerBatch)
{
    __shared__ uint2 sbox[NBOX];                     // {x1|x2<<16, y1|y2<<16}
    __shared__ float sc  [NBOX];                     // 0.5 * conf
    __shared__ float4 rows4[NWARPS * 2][ROW_V4];     // 2 build rows per warp
    __shared__ uint2 ev  [ROWS_PER_BLOCK][EVCAP];    // per-row event buckets
    __shared__ int   evn [ROWS_PER_BLOCK];
    __shared__ unsigned long long rowMaskS, ovMaskS;

    const int b       = blockIdx.x / blocksPerBatch;
    const int rowBase = (blockIdx.x % blocksPerBatch) * ROWS_PER_BLOCK;
    const int tid     = threadIdx.x;
    const int warp    = tid >> 5;
    const int lane    = tid & 31;

    if (tid < ROWS_PER_BLOCK) evn[tid] = 0;
    if (tid == 0) { rowMaskS = 0ull; ovMaskS = 0ull; }
    __syncthreads();

    // ---- load + quantize boxes; bucket in-block enter/exit events ----
    for (int i = tid; i < NBOX; i += 128) {
        const float* p = preds + ((size_t)b * NBOX + i) * 5;
        float c  = p[0];
        int x1 = min(max((int)floorf(p[1] * 512.0f), 0), FEAT);
        int y1 = min(max((int)floorf(p[2] * 512.0f), 0), FEAT);
        int x2 = min(max((int)floorf(p[3] * 512.0f), 0), FEAT);
        int y2 = min(max((int)floorf(p[4] * 512.0f), 0), FEAT);
        if (!((x2 > x1) && (y2 > y1))) { y1 = 0; y2 = 0; }   // empty y-range
        sbox[i] = make_uint2((unsigned)(x1 | (x2 << 16)),
                             (unsigned)(y1 | (y2 << 16)));
        float hc = 0.5f * c;                                  // pre-halved
        sc[i] = hc;

        unsigned xp = (unsigned)x1 | ((unsigned)x2 << 10);
        int d1 = y1 - rowBase;                                // enter
        if (d1 > 0 && d1 < ROWS_PER_BLOCK && (d1 & (CHUNK - 1))) {
            atomicOr(&rowMaskS, 1ull << d1);
            int e = atomicAdd(&evn[d1], 1);
            if (e < EVCAP) ev[d1][e] = make_uint2(xp, __float_as_uint(hc));
            else           atomicOr(&ovMaskS, 1ull << d1);
        }
        int d2 = y2 - rowBase;                                // exit
        if (d2 > 0 && d2 < ROWS_PER_BLOCK && (d2 & (CHUNK - 1))) {
            atomicOr(&rowMaskS, 1ull << d2);
            int e = atomicAdd(&evn[d2], 1);
            if (e < EVCAP) ev[d2][e] = make_uint2(xp, __float_as_uint(-hc));
            else           atomicOr(&ovMaskS, 1ull << d2);
        }
    }
    __syncthreads();
    const unsigned long long rowMask = rowMaskS;
    const unsigned long long ovMask  = ovMaskS;

    // warp owns block-rows [8w, 8w+8) (chunk A) and [32+8w, 32+8w+8) (chunk B)
    const int rA = warp * CHUNK;              // block-row of anchor A
    const int rB = rA + 32;                   // block-row of anchor B
    const int y0A = rowBase + rA;
    const int y0B = rowBase + rB;
    float4* rowA4 = rows4[warp * 2];
    float4* rowB4 = rows4[warp * 2 + 1];
    float*  rowA  = (float*)rowA4;
    float*  rowB  = (float*)rowB4;

    // ---- zero both build rows ----
    #pragma unroll
    for (int i = lane; i < ROW_V4; i += 32) {
        rowA4[i] = make_float4(0.f, 0.f, 0.f, 0.f);
        rowB4[i] = make_float4(0.f, 0.f, 0.f, 0.f);
    }
    __syncwarp();

    // ---- one pass over boxes: scatter into both anchors ----
    #pragma unroll
    for (int i = lane; i < NBOX; i += 32) {
        uint2 bx = sbox[i];
        int y1 = (int)(bx.y & 0xFFFF), y2 = (int)(bx.y >> 16);
        float hc = sc[i];
        int w1 = padw((int)(bx.x & 0xFFFF));
        int w2 = padw((int)(bx.x >> 16));
        if (y1 <= y0A && y0A < y2) {
            atomicAdd(&rowA[w1],  hc);
            atomicAdd(&rowA[w2], -hc);
        }
        if (y1 <= y0B && y0B < y2) {
            atomicAdd(&rowB[w1],  hc);
            atomicAdd(&rowB[w2], -hc);
        }
    }
    __syncwarp();

    // ---- scan both rows into registers (interleaved, conflict-free) ----
    float vA[16], vB[16];
    {
        const int base4 = lane * 5;           // word 20*lane (80B stride)
        float4 fA[4], fB[4];
        #pragma unroll
        for (int k = 0; k < 4; k++) { fA[k] = rowA4[base4 + k]; fB[k] = rowB4[base4 + k]; }
        const float* fa = (const float*)fA;
        const float* fb = (const float*)fB;
        float runA = 0.0f, runB = 0.0f;
        #pragma unroll
        for (int j = 0; j < 16; j++) {
            runA += fa[j]; vA[j] = runA;
            runB += fb[j]; vB[j] = runB;
        }
        float xA = runA, xB = runB;
        #pragma unroll
        for (int o = 1; o < 32; o <<= 1) {
            float tA = __shfl_up_sync(0xFFFFFFFFu, xA, o);
            float tB = __shfl_up_sync(0xFFFFFFFFu, xB, o);
            if (lane >= o) { xA += tA; xB += tB; }
        }
        float preA = __shfl_up_sync(0xFFFFFFFFu, xA, 1);
        float preB = __shfl_up_sync(0xFFFFFFFFu, xB, 1);
        if (lane == 0) { preA = 0.0f; preB = 0.0f; }
        #pragma unroll
        for (int j = 0; j < 16; j++) { vA[j] += preA; vB[j] += preB; }
    }

    // ---- per-row: sigmoid + store both chunks, then apply next-row events ----
    const int s = lane * 16;
    float* dstA = out + (((size_t)b * FEAT + y0A) * FEAT) + s;
    float* dstB = out + (((size_t)b * FEAT + y0B) * FEAT) + s;

    for (int r = 0; r < CHUNK; r++) {
        // hoist next-row event counts (broadcast LDS) above the MUFU/STG block
        const int tA = rA + r + 1, tB = rB + r + 1;
        int nA = 0, nB = 0;
        bool haveA = false, haveB = false;
        if (r + 1 < CHUNK) {
            haveA = (rowMask >> tA) & 1ull;
            haveB = (rowMask >> tB) & 1ull;
            if (haveA) nA = evn[tA];
            if (haveB) nB = evn[tB];
        }

        float4* dA = (float4*)(dstA + (size_t)r * FEAT);
        float4* dB = (float4*)(dstB + (size_t)r * FEAT);
        #pragma unroll
        for (int g = 0; g < 4; g++) {
            float4 a4, b4;
            float* ap = (float*)&a4;
            float* bp = (float*)&b4;
            #pragma unroll
            for (int j = 0; j < 4; j++) {
                float ta, tb;
                asm("tanh.approx.f32 %0, %1;" : "=f"(ta) : "f"(vA[g * 4 + j]));
                asm("tanh.approx.f32 %0, %1;" : "=f"(tb) : "f"(vB[g * 4 + j]));
                ap[j] = fmaf(0.5f, ta, 0.5f);
                bp[j] = fmaf(0.5f, tb, 0.5f);
            }
            dA[g] = a4;
            dB[g] = b4;
        }

        if (r + 1 < CHUNK) {
            // chunk A events
            if (haveA) {
                if (!((ovMask >> tA) & 1ull)) {
                    for (int k = 0; k < nA; k++) {
                        uint2 e = ev[tA][k];
                        int lo = max((int)(e.x & 0x3FF) - s, 0);
                        int hi = min((int)((e.x >> 10) & 0x3FF) - s, 16);
                        float c2 = __uint_as_float(e.y);
                        if (lo < hi) {
                            #pragma unroll
                            for (int j = 0; j < 16; j++)
                                if (j >= lo && j < hi) vA[j] += c2;
                        }
                    }
                } else {
                    const int yt = y0A + r + 1;
                    for (int i = 0; i < NBOX; i++) {
                        uint2 bx = sbox[i];
                        int y1 = (int)(bx.y & 0xFFFF), y2 = (int)(bx.y >> 16);
                        bool en = (y1 == yt), ex = (y2 == yt && y2 > y1);
                        if (en || ex) {
                            float c2 = en ? sc[i] : -sc[i];
                            int lo = max((int)(bx.x & 0xFFFF) - s, 0);
                            int hi = min((int)(bx.x >> 16) - s, 16);
                            if (lo < hi) {
                                #pragma unroll
                                for (int j = 0; j < 16; j++)
                                    if (j >= lo && j < hi) vA[j] += c2;
                            }
                        }
                    }
                }
            }
            // chunk B events
            if (haveB) {
                if (!((ovMask >> tB) & 1ull)) {
                    for (int k = 0; k < nB; k++) {
                        uint2 e = ev[tB][k];
                        int lo = max((int)(e.x & 0x3FF) - s, 0);
                        int hi = min((int)((e.x >> 10) & 0x3FF) - s, 16);
                        float c2 = __uint_as_float(e.y);
                        if (lo < hi) {
                            #pragma unroll
                            for (int j = 0; j < 16; j++)
                                if (j >= lo && j < hi) vB[j] += c2;
                        }
                    }
                } else {
                    const int yt = y0B + r + 1;
                    for (int i = 0; i < NBOX; i++) {
                        uint2 bx = sbox[i];
                        int y1 = (int)(bx.y & 0xFFFF), y2 = (int)(bx.y >> 16);
                        bool en = (y1 == yt), ex = (y2 == yt && y2 > y1);
                        if (en || ex) {
                            float c2 = en ? sc[i] : -sc[i];
                            int lo = max((int)(bx.x & 0xFFFF) - s, 0);
                            int hi = min((int)(bx.x >> 16) - s, 16);
                            if (lo < hi) {
                                #pragma unroll
                                for (int j = 0; j < 16; j++)
                                    if (j >= lo && j < hi) vB[j] += c2;
                            }
                        }
                    }
                }
            }
        }
    }
}

extern "C" void kernel_launch(void* const* d_in, const int* in_sizes, int n_in,
                              void* d_out, int out_size)
{
    const float* preds = (const float*)d_in[0];
    float* out = (float*)d_out;

    int B = in_sizes[0] / (NBOX * 5);               // 64 for bench shapes
    int blocksPerBatch = FEAT / ROWS_PER_BLOCK;     // 8
    dim3 grid(B * blocksPerBatch);                  // 512
    dim3 block(128);
    bbox_att_kernel<<<grid, block>>>(preds, out, blocksPerBatch);
}

// round 9
// speedup vs baseline: 1.1231x; 1.1231x over previous
#include <cuda_runtime.h>
#include <cuda_bf16.h>
#include <math.h>

// BboxSemanticAtt: out[b,y,x] = sigmoid( sum_i c_i * [y1<=y<y2][x1<=x<x2] )
// preds: [B, 256, 5] f32; out: [B, 512, 512] f32.
//
// ONE build per block (amortizes the LSU-heavy smem scatter 4x): warp 0
// corner-scatters + scans the block anchor row and stores the scanned row to
// smem; warps 1-3 load it and catch up to their own anchor by applying
// bucketed events (broadcast LDS + predicated FADD, no atomics). Then each
// warp walks its 8 rows incrementally. v holds g/2 (conf pre-halved);
// sigmoid = 0.5*tanh(v)+0.5 (1 MUFU).

#define FEAT   512
#define NBOX   256
#define NWARPS 4
#define CHUNK  8
#define ROWS_PER_BLOCK 32                  // 4 warps x 8 rows
#define ROW_V4   161                       // 644 padded words / 4
#define EVCAP  8

__device__ __forceinline__ int padw(int p) { return p + ((p >> 4) << 2); }

__global__ __launch_bounds__(128, 12)
void bbox_att_kernel(const float* __restrict__ preds,
                     float* __restrict__ out,
                     int blocksPerBatch)
{
    __shared__ uint2 sbox[NBOX];                     // {x1|x2<<16, y1|y2<<16}
    __shared__ float sc  [NBOX];                     // 0.5 * conf
    __shared__ float4 brow4[ROW_V4];                 // build row -> scanned row
    __shared__ uint2 ev  [ROWS_PER_BLOCK][EVCAP];    // per-row event buckets
    __shared__ int   evn [ROWS_PER_BLOCK];
    __shared__ unsigned rowMaskS, ovMaskS;

    const int b       = blockIdx.x / blocksPerBatch;
    const int rowBase = (blockIdx.x % blocksPerBatch) * ROWS_PER_BLOCK;
    const int tid     = threadIdx.x;
    const int warp    = tid >> 5;
    const int lane    = tid & 31;

    if (tid < ROWS_PER_BLOCK) evn[tid] = 0;
    if (tid == 0) { rowMaskS = 0u; ovMaskS = 0u; }
    __syncthreads();

    // ---- load + quantize boxes; bucket ALL in-block enter/exit events ----
    for (int i = tid; i < NBOX; i += 128) {
        const float* p = preds + ((size_t)b * NBOX + i) * 5;
        float c  = p[0];
        int x1 = min(max((int)floorf(p[1] * 512.0f), 0), FEAT);
        int y1 = min(max((int)floorf(p[2] * 512.0f), 0), FEAT);
        int x2 = min(max((int)floorf(p[3] * 512.0f), 0), FEAT);
        int y2 = min(max((int)floorf(p[4] * 512.0f), 0), FEAT);
        if (!((x2 > x1) && (y2 > y1))) { y1 = 0; y2 = 0; }   // empty y-range
        sbox[i] = make_uint2((unsigned)(x1 | (x2 << 16)),
                             (unsigned)(y1 | (y2 << 16)));
        float hc = 0.5f * c;                                  // pre-halved
        sc[i] = hc;

        unsigned xp = (unsigned)x1 | ((unsigned)x2 << 10);
        int d1 = y1 - rowBase;                                // enter
        if (d1 > 0 && d1 < ROWS_PER_BLOCK) {
            atomicOr(&rowMaskS, 1u << d1);
            int e = atomicAdd(&evn[d1], 1);
            if (e < EVCAP) ev[d1][e] = make_uint2(xp, __float_as_uint(hc));
            else           atomicOr(&ovMaskS, 1u << d1);
        }
        int d2 = y2 - rowBase;                                // exit
        if (d2 > 0 && d2 < ROWS_PER_BLOCK) {
            atomicOr(&rowMaskS, 1u << d2);
            int e = atomicAdd(&evn[d2], 1);
            if (e < EVCAP) ev[d2][e] = make_uint2(xp, __float_as_uint(-hc));
            else           atomicOr(&ovMaskS, 1u << d2);
        }
    }
    __syncthreads();
    const unsigned rowMask = rowMaskS;
    const unsigned ovMask  = ovMaskS;

    const int s = lane * 16;
    float v[16];

    // ---- warp 0: build + scan the block anchor row (rowBase), store scan ----
    if (warp == 0) {
        float* brow = (float*)brow4;
        #pragma unroll
        for (int i = lane; i < ROW_V4; i += 32)
            brow4[i] = make_float4(0.f, 0.f, 0.f, 0.f);
        __syncwarp();

        #pragma unroll
        for (int i = lane; i < NBOX; i += 32) {
            uint2 bx = sbox[i];
            int y1 = (int)(bx.y & 0xFFFF), y2 = (int)(bx.y >> 16);
            if (y1 <= rowBase && rowBase < y2) {
                float hc = sc[i];
                atomicAdd(&brow[padw((int)(bx.x & 0xFFFF))],  hc);
                atomicAdd(&brow[padw((int)(bx.x >> 16))],    -hc);
            }
        }
        __syncwarp();

        // scan (4x LDS.128, 80B lane stride: conflict-free)
        const int base4 = lane * 5;
        float4 f[4];
        #pragma unroll
        for (int k = 0; k < 4; k++) f[k] = brow4[base4 + k];
        const float* fs = (const float*)f;
        float run = 0.0f;
        #pragma unroll
        for (int j = 0; j < 16; j++) { run += fs[j]; v[j] = run; }

        float x = run;
        #pragma unroll
        for (int o = 1; o < 32; o <<= 1) {
            float t = __shfl_up_sync(0xFFFFFFFFu, x, o);
            if (lane >= o) x += t;
        }
        float pre = __shfl_up_sync(0xFFFFFFFFu, x, 1);
        if (lane == 0) pre = 0.0f;
        #pragma unroll
        for (int j = 0; j < 16; j++) v[j] += pre;

        // write scanned row back (4x STS.128, same layout)
        #pragma unroll
        for (int k = 0; k < 4; k++) brow4[base4 + k] = ((float4*)v)[k];
    }
    __syncthreads();

    // ---- warps 1-3: load scanned row, catch up to own anchor via events ----
    if (warp != 0) {
        const int base4 = lane * 5;
        #pragma unroll
        for (int k = 0; k < 4; k++) ((float4*)v)[k] = brow4[base4 + k];

        const int upto = warp * CHUNK;                 // apply offsets [1, upto]
        unsigned m = rowMask & ((2u << upto) - 2u);    // bits 1..upto
        while (m) {
            int t = __ffs(m) - 1; m &= m - 1;
            if (!((ovMask >> t) & 1u)) {
                const int n = evn[t];
                for (int k = 0; k < n; k++) {
                    uint2 e = ev[t][k];
                    int lo = max((int)(e.x & 0x3FF) - s, 0);
                    int hi = min((int)((e.x >> 10) & 0x3FF) - s, 16);
                    float c2 = __uint_as_float(e.y);
                    if (lo < hi) {
                        #pragma unroll
                        for (int j = 0; j < 16; j++)
                            if (j >= lo && j < hi) v[j] += c2;
                    }
                }
            } else {                                   // rare overflow: rescan
                const int yt = rowBase + t;
                for (int i = 0; i < NBOX; i++) {
                    uint2 bx = sbox[i];
                    int y1 = (int)(bx.y & 0xFFFF), y2 = (int)(bx.y >> 16);
                    bool en = (y1 == yt), ex = (y2 == yt && y2 > y1);
                    if (en || ex) {
                        float c2 = en ? sc[i] : -sc[i];
                        int lo = max((int)(bx.x & 0xFFFF) - s, 0);
                        int hi = min((int)(bx.x >> 16) - s, 16);
                        if (lo < hi) {
                            #pragma unroll
                            for (int j = 0; j < 16; j++)
                                if (j >= lo && j < hi) v[j] += c2;
                        }
                    }
                }
            }
        }
    }

    // ---- per-row: sigmoid + store, then apply next row's events ----
    const int y0 = rowBase + warp * CHUNK;
    float* dstBase = out + (((size_t)b * FEAT + y0) * FEAT) + s;

    for (int r = 0; r < CHUNK; r++) {
        float4* dst = (float4*)(dstBase + (size_t)r * FEAT);
        #pragma unroll
        for (int g = 0; g < 4; g++) {
            float4 t4;
            float* tp = (float*)&t4;
            #pragma unroll
            for (int j = 0; j < 4; j++) {
                float t;
                asm("tanh.approx.f32 %0, %1;" : "=f"(t) : "f"(v[g * 4 + j]));
                tp[j] = fmaf(0.5f, t, 0.5f);
            }
            dst[g] = t4;
        }

        if (r + 1 < CHUNK) {
            const int target = warp * CHUNK + r + 1;   // block-row offset
            if ((rowMask >> target) & 1u) {
                if (!((ovMask >> target) & 1u)) {
                    const int n = evn[target];
                    for (int k = 0; k < n; k++) {
                        uint2 e = ev[target][k];
                        int lo = max((int)(e.x & 0x3FF) - s, 0);
                        int hi = min((int)((e.x >> 10) & 0x3FF) - s, 16);
                        float c2 = __uint_as_float(e.y);
                        if (lo < hi) {
                            #pragma unroll
                            for (int j = 0; j < 16; j++)
                                if (j >= lo && j < hi) v[j] += c2;
                        }
                    }
                } else {                               // rare overflow: rescan
                    const int yt = y0 + r + 1;
                    for (int i = 0; i < NBOX; i++) {
                        uint2 bx = sbox[i];
                        int y1 = (int)(bx.y & 0xFFFF), y2 = (int)(bx.y >> 16);
                        bool en = (y1 == yt), ex = (y2 == yt && y2 > y1);
                        if (en || ex) {
                            float c2 = en ? sc[i] : -sc[i];
                            int lo = max((int)(bx.x & 0xFFFF) - s, 0);
                            int hi = min((int)(bx.x >> 16) - s, 16);
                            if (lo < hi) {
                                #pragma unroll
                                for (int j = 0; j < 16; j++)
                                    if (j >= lo && j < hi) v[j] += c2;
                            }
                        }
                    }
                }
            }
        }
    }
}

extern "C" void kernel_launch(void* const* d_in, const int* in_sizes, int n_in,
                              void* d_out, int out_size)
{
    const float* preds = (const float*)d_in[0];
    float* out = (float*)d_out;

    int B = in_sizes[0] / (NBOX * 5);               // 64 for bench shapes
    int blocksPerBatch = FEAT / ROWS_PER_BLOCK;     // 16
    dim3 grid(B * blocksPerBatch);                  // 1024
    dim3 block(128);
    bbox_att_kernel<<<grid, block>>>(preds, out, blocksPerBatch);
}

// round 10
// speedup vs baseline: 1.8041x; 1.6064x over previous
#include <cuda_runtime.h>
#include <cuda_bf16.h>
#include <math.h>

// BboxSemanticAtt: out[b,y,x] = sigmoid( sum_i c_i * [y1<=y<y2][x1<=x<x2] )
// preds: [B, 256, 5] f32; out: [B, 512, 512] f32.
//
// Transposed column ownership for DENSE stores: lane l owns quads
// [128g+4l, 128g+4l+4), g=0..3, so each STG.128 is a contiguous 512B burst
// (was: 16B per lane strided 64B = 25%-dense lines -> 4x store wavefronts).
// One build per block: warp 0 corner-scatters + scans the anchor row, stores
// the scanned row; warps 1-3 catch up via bucketed events (broadcast LDS).
// v holds g/2 (conf pre-halved); sigmoid = 0.5*tanh(v)+0.5 (1 MUFU).

#define FEAT   512
#define NBOX   256
#define CHUNK  8
#define ROWS_PER_BLOCK 32                  // 4 warps x 8 rows
#define ROW_WORDS 516                      // 512 + slot for x2=512 (+ pad)
#define EVCAP  8

__global__ __launch_bounds__(128, 12)
void bbox_att_kernel(const float* __restrict__ preds,
                     float* __restrict__ out,
                     int blocksPerBatch)
{
    __shared__ uint2 sbox[NBOX];                     // {x1|x2<<16, y1|y2<<16}
    __shared__ float sc  [NBOX];                     // 0.5 * conf
    __shared__ float brow[ROW_WORDS];                // build row -> scanned row
    __shared__ uint2 ev  [ROWS_PER_BLOCK][EVCAP];    // per-row event buckets
    __shared__ int   evn [ROWS_PER_BLOCK];
    __shared__ unsigned rowMaskS, ovMaskS;

    const int b       = blockIdx.x / blocksPerBatch;
    const int rowBase = (blockIdx.x % blocksPerBatch) * ROWS_PER_BLOCK;
    const int tid     = threadIdx.x;
    const int warp    = tid >> 5;
    const int lane    = tid & 31;

    if (tid < ROWS_PER_BLOCK) evn[tid] = 0;
    if (tid == 0) { rowMaskS = 0u; ovMaskS = 0u; }
    __syncthreads();

    // ---- load + quantize boxes; bucket ALL in-block enter/exit events ----
    for (int i = tid; i < NBOX; i += 128) {
        const float* p = preds + ((size_t)b * NBOX + i) * 5;
        float c  = p[0];
        int x1 = min(max((int)floorf(p[1] * 512.0f), 0), FEAT);
        int y1 = min(max((int)floorf(p[2] * 512.0f), 0), FEAT);
        int x2 = min(max((int)floorf(p[3] * 512.0f), 0), FEAT);
        int y2 = min(max((int)floorf(p[4] * 512.0f), 0), FEAT);
        if (!((x2 > x1) && (y2 > y1))) { y1 = 0; y2 = 0; }   // empty y-range
        sbox[i] = make_uint2((unsigned)(x1 | (x2 << 16)),
                             (unsigned)(y1 | (y2 << 16)));
        float hc = 0.5f * c;                                  // pre-halved
        sc[i] = hc;

        unsigned xp = (unsigned)x1 | ((unsigned)x2 << 10);
        int d1 = y1 - rowBase;                                // enter
        if (d1 > 0 && d1 < ROWS_PER_BLOCK) {
            atomicOr(&rowMaskS, 1u << d1);
            int e = atomicAdd(&evn[d1], 1);
            if (e < EVCAP) ev[d1][e] = make_uint2(xp, __float_as_uint(hc));
            else           atomicOr(&ovMaskS, 1u << d1);
        }
        int d2 = y2 - rowBase;                                // exit
        if (d2 > 0 && d2 < ROWS_PER_BLOCK) {
            atomicOr(&rowMaskS, 1u << d2);
            int e = atomicAdd(&evn[d2], 1);
            if (e < EVCAP) ev[d2][e] = make_uint2(xp, __float_as_uint(-hc));
            else           atomicOr(&ovMaskS, 1u << d2);
        }
    }
    __syncthreads();
    const unsigned rowMask = rowMaskS;
    const unsigned ovMask  = ovMaskS;

    // v[4g+j] = half-sum for column (128g + 4*lane + j)
    float v[16];
    float4* brow4 = (float4*)brow;

    // ---- warp 0: build + scan the block anchor row (rowBase) ----
    if (warp == 0) {
        #pragma unroll
        for (int i = lane; i < ROW_WORDS / 4; i += 32)
            brow4[i] = make_float4(0.f, 0.f, 0.f, 0.f);
        __syncwarp();

        #pragma unroll
        for (int i = lane; i < NBOX; i += 32) {
            uint2 bx = sbox[i];
            int y1 = (int)(bx.y & 0xFFFF), y2 = (int)(bx.y >> 16);
            if (y1 <= rowBase && rowBase < y2) {
                float hc = sc[i];
                atomicAdd(&brow[(int)(bx.x & 0xFFFF)],  hc);
                atomicAdd(&brow[(int)(bx.x >> 16)],    -hc);
            }
        }
        __syncwarp();

        // quad-local scans + per-g warp scans + cross-g offsets
        float4 f[4];
        #pragma unroll
        for (int g = 0; g < 4; g++) f[g] = brow4[g * 32 + lane];
        const float* fs = (const float*)f;
        float incl[4];
        #pragma unroll
        for (int g = 0; g < 4; g++) {
            float run = 0.0f;
            #pragma unroll
            for (int j = 0; j < 4; j++) { run += fs[g * 4 + j]; v[g * 4 + j] = run; }
            incl[g] = run;
        }
        #pragma unroll
        for (int o = 1; o < 32; o <<= 1) {
            float t0 = __shfl_up_sync(0xFFFFFFFFu, incl[0], o);
            float t1 = __shfl_up_sync(0xFFFFFFFFu, incl[1], o);
            float t2 = __shfl_up_sync(0xFFFFFFFFu, incl[2], o);
            float t3 = __shfl_up_sync(0xFFFFFFFFu, incl[3], o);
            if (lane >= o) { incl[0] += t0; incl[1] += t1; incl[2] += t2; incl[3] += t3; }
        }
        float off = 0.0f;
        #pragma unroll
        for (int g = 0; g < 4; g++) {
            float e = __shfl_up_sync(0xFFFFFFFFu, incl[g], 1);
            if (lane == 0) e = 0.0f;
            float add = off + e;
            #pragma unroll
            for (int j = 0; j < 4; j++) v[g * 4 + j] += add;
            off += __shfl_sync(0xFFFFFFFFu, incl[g], 31);     // total of group g
        }

        // write scanned row back (dense STS.128, same layout)
        #pragma unroll
        for (int g = 0; g < 4; g++) brow4[g * 32 + lane] = ((float4*)v)[g];
    }
    __syncthreads();

    // ---- warps 1-3: load scanned row, catch up to own anchor via events ----
    if (warp != 0) {
        #pragma unroll
        for (int g = 0; g < 4; g++) ((float4*)v)[g] = brow4[g * 32 + lane];

        const int upto = warp * CHUNK;                 // apply offsets [1, upto]
        unsigned m = rowMask & ((2u << upto) - 2u);    // bits 1..upto
        while (m) {
            int t = __ffs(m) - 1; m &= m - 1;
            if (!((ovMask >> t) & 1u)) {
                const int n = evn[t];
                for (int k = 0; k < n; k++) {
                    uint2 e = ev[t][k];
                    int x1 = (int)(e.x & 0x3FF);
                    int x2 = (int)((e.x >> 10) & 0x3FF);
                    float c2 = __uint_as_float(e.y);
                    #pragma unroll
                    for (int g = 0; g < 4; g++) {
                        int base = g * 128 + 4 * lane;
                        int lo = max(x1 - base, 0), hi = min(x2 - base, 4);
                        if (lo < hi) {
                            #pragma unroll
                            for (int j = 0; j < 4; j++)
                                if (j >= lo && j < hi) v[g * 4 + j] += c2;
                        }
                    }
                }
            } else {                                   // rare overflow: rescan
                const int yt = rowBase + t;
                for (int i = 0; i < NBOX; i++) {
                    uint2 bx = sbox[i];
                    int y1 = (int)(bx.y & 0xFFFF), y2 = (int)(bx.y >> 16);
                    bool en = (y1 == yt), ex = (y2 == yt && y2 > y1);
                    if (en || ex) {
                        float c2 = en ? sc[i] : -sc[i];
                        int x1 = (int)(bx.x & 0xFFFF);
                        int x2 = (int)(bx.x >> 16);
                        #pragma unroll
                        for (int g = 0; g < 4; g++) {
                            int base = g * 128 + 4 * lane;
                            int lo = max(x1 - base, 0), hi = min(x2 - base, 4);
                            if (lo < hi) {
                                #pragma unroll
                                for (int j = 0; j < 4; j++)
                                    if (j >= lo && j < hi) v[g * 4 + j] += c2;
                            }
                        }
                    }
                }
            }
        }
    }

    // ---- per-row: sigmoid + DENSE store, then apply next row's events ----
    const int y0 = rowBase + warp * CHUNK;
    float4* dstRow = (float4*)(out + (((size_t)b * FEAT + y0) * FEAT));

    for (int r = 0; r < CHUNK; r++) {
        float4* dst = dstRow + (size_t)r * (FEAT / 4);
        #pragma unroll
        for (int g = 0; g < 4; g++) {
            float4 t4;
            float* tp = (float*)&t4;
            #pragma unroll
            for (int j = 0; j < 4; j++) {
                float t;
                asm("tanh.approx.f32 %0, %1;" : "=f"(t) : "f"(v[g * 4 + j]));
                tp[j] = fmaf(0.5f, t, 0.5f);
            }
            dst[g * 32 + lane] = t4;    // consecutive lanes 16B apart: dense 512B
        }

        if (r + 1 < CHUNK) {
            const int target = warp * CHUNK + r + 1;   // block-row offset
            if ((rowMask >> target) & 1u) {
                if (!((ovMask >> target) & 1u)) {
                    const int n = evn[target];
                    for (int k = 0; k < n; k++) {
                        uint2 e = ev[target][k];
                        int x1 = (int)(e.x & 0x3FF);
                        int x2 = (int)((e.x >> 10) & 0x3FF);
                        float c2 = __uint_as_float(e.y);
                        #pragma unroll
                        for (int g = 0; g < 4; g++) {
                            int base = g * 128 + 4 * lane;
                            int lo = max(x1 - base, 0), hi = min(x2 - base, 4);
                            if (lo < hi) {
                                #pragma unroll
                                for (int j = 0; j < 4; j++)
                                    if (j >= lo && j < hi) v[g * 4 + j] += c2;
                            }
                        }
                    }
                } else {                               // rare overflow: rescan
                    const int yt = y0 + r + 1;
                    for (int i = 0; i < NBOX; i++) {
                        uint2 bx = sbox[i];
                        int y1 = (int)(bx.y & 0xFFFF), y2 = (int)(bx.y >> 16);
                        bool en = (y1 == yt), ex = (y2 == yt && y2 > y1);
                        if (en || ex) {
                            float c2 = en ? sc[i] : -sc[i];
                            int x1 = (int)(bx.x & 0xFFFF);
                            int x2 = (int)(bx.x >> 16);
                            #pragma unroll
                            for (int g = 0; g < 4; g++) {
                                int base = g * 128 + 4 * lane;
                                int lo = max(x1 - base, 0), hi = min(x2 - base, 4);
                                if (lo < hi) {
                                    #pragma unroll
                                    for (int j = 0; j < 4; j++)
                                        if (j >= lo && j < hi) v[g * 4 + j] += c2;
                                }
                            }
                        }
                    }
                }
            }
        }
    }
}

extern "C" void kernel_launch(void* const* d_in, const int* in_sizes, int n_in,
                              void* d_out, int out_size)
{
    const float* preds = (const float*)d_in[0];
    float* out = (float*)d_out;

    int B = in_sizes[0] / (NBOX * 5);               // 64 for bench shapes
    int blocksPerBatch = FEAT / ROWS_PER_BLOCK;     // 16
    dim3 grid(B * blocksPerBatch);                  // 1024
    dim3 block(128);
    bbox_att_kernel<<<grid, block>>>(preds, out, blocksPerBatch);
}